// round 12
// baseline (speedup 1.0000x reference)
#include <cuda_runtime.h>
#include <math.h>

#define IH 256
#define IW 704
#define FH 32
#define FW 88
#define PIX (FH*FW)          // 2816
#define BATCH 2
#define C_IN 256
#define HID 64
#define DEPTH 118
#define C_OUT 80
#define OUT2 (DEPTH + C_OUT) // 198
#define NR 128
#define NT 256
#define NRT (NR*NT)          // 32768
#define PI_D 3.141592653589793
#define VST 204              // vsh row stride (feat at +120)
#define FOFF 120
#define DPAD 120             // g_depth per-pixel stride
#define DST 121              // dsh row stride (conflict-free)
#define FST 40               // fsh row stride

typedef unsigned long long u64;

// ---------------- device scratch ----------------
__device__ float g_h[BATCH*PIX*HID];             // [b][pix][hid]
__device__ __align__(16) float g_w2f[OUT2*HID];  // BN-folded w2
__device__ float g_c2[OUT2];
__device__ float g_radE[NR+1];
__device__ float g_angE[NT+1];
__device__ __align__(16) float g_depth[BATCH*PIX*DPAD];
__device__ __align__(16) float g_feat[BATCH*PIX*C_OUT];

// ---------------- f32x2 helpers ----------------
__device__ __forceinline__ void fma2(u64& d, u64 a, u64 b) {
    asm("fma.rn.f32x2 %0, %1, %2, %3;" : "=l"(d) : "l"(a), "l"(b), "l"(d));
}
__device__ __forceinline__ float2 unpack2(u64 v) {
    float2 r; asm("mov.b64 {%0,%1}, %2;" : "=f"(r.x), "=f"(r.y) : "l"(v)); return r;
}
__device__ __forceinline__ void redadd(float* p, float v) {
    asm volatile("red.global.add.f32 [%0], %1;" :: "l"(p), "f"(v) : "memory");
}

// ---------------- K1: GEMM1 + zero d_out + precompute tables / folded w2 ----------------
__global__ void __launch_bounds__(256) k1_gemm1(const float* __restrict__ x,
                                                const float* __restrict__ w1,
                                                const float* __restrict__ b1,
                                                const float* __restrict__ g1,
                                                const float* __restrict__ be1,
                                                const float* __restrict__ m1,
                                                const float* __restrict__ v1,
                                                const float* __restrict__ w2,
                                                const float* __restrict__ b2,
                                                const float* __restrict__ g2,
                                                const float* __restrict__ be2,
                                                const float* __restrict__ m2,
                                                const float* __restrict__ v2,
                                                float* __restrict__ outz)
{
    __shared__ float xs[64*16];      // [c][pix]
    __shared__ float ws[64*65];      // [c][o], stride 65

    int blk = blockIdx.x, t = threadIdx.x;

    if (blk >= 352) {
        if (blk < 480) {
            int base = (blk - 352) * 10240;
            float4 z = make_float4(0.f,0.f,0.f,0.f);
#pragma unroll 4
            for (int i = t; i < 10240; i += 256)
                ((float4*)outz)[base + i] = z;
        } else if (blk == 480) {
            if (t <= NR) {
                double tt = (double)t * (1.0/128.0);
                g_radE[t] = (float)(1.0 + pow(tt, 1.5) * 59.0);
            }
            for (int i = t; i <= NT; i += 256) {
                double a = (i == NT) ? (PI_D*0.5) : (-PI_D*0.5 + (double)i * (PI_D/256.0));
                g_angE[i] = (float)a;
            }
            if (t < OUT2) {
                float inv = g2[t] / sqrtf(v2[t] + 1e-5f);
                g_c2[t] = b2[t]*inv + be2[t] - m2[t]*inv;
            }
        } else {
            int base = (blk - 481) * 396;
            for (int j = base + t; j < base + 396; j += 256) {
                int o = j >> 4;
                float inv = g2[o] / sqrtf(v2[o] + 1e-5f);
                float4 w = ((const float4*)w2)[j];
                w.x *= inv; w.y *= inv; w.z *= inv; w.w *= inv;
                ((float4*)g_w2f)[j] = w;
            }
        }
        return;
    }

    int b = blk / 176;
    int pixbase = (blk % 176) * 16;
    int o  = t & 63;
    int pg = t >> 6;

    float4 acc = make_float4(0.f,0.f,0.f,0.f);

    for (int cc = 0; cc < 4; cc++) {
        __syncthreads();
        {
            int c = t >> 2, p4 = t & 3;
            ((float4*)xs)[t] = ((const float4*)(x + (b*C_IN + cc*64 + c)*PIX + pixbase))[p4];
        }
#pragma unroll
        for (int i = 0; i < 4; i++) {
            int j = t + i*256;
            int oo = j >> 4, k4 = j & 15;
            float4 w = *(const float4*)(w1 + oo*C_IN + cc*64 + k4*4);
            ws[(k4*4+0)*65 + oo] = w.x;
            ws[(k4*4+1)*65 + oo] = w.y;
            ws[(k4*4+2)*65 + oo] = w.z;
            ws[(k4*4+3)*65 + oo] = w.w;
        }
        __syncthreads();
#pragma unroll 8
        for (int cl = 0; cl < 64; cl++) {
            float w = ws[cl*65 + o];
            float4 xv = *(const float4*)&xs[cl*16 + pg*4];
            acc.x += w*xv.x; acc.y += w*xv.y; acc.z += w*xv.z; acc.w += w*xv.w;
        }
    }
    float inv  = g1[o] / sqrtf(v1[o] + 1e-5f);
    float bias = b1[o]*inv + be1[o] - m1[o]*inv;
    int pbase = b*PIX + pixbase + pg*4;
    g_h[(pbase+0)*HID + o] = fmaxf(acc.x*inv + bias, 0.f);
    g_h[(pbase+1)*HID + o] = fmaxf(acc.y*inv + bias, 0.f);
    g_h[(pbase+2)*HID + o] = fmaxf(acc.z*inv + bias, 0.f);
    g_h[(pbase+3)*HID + o] = fmaxf(acc.w*inv + bias, 0.f);
}

// =========== K2: GEMM2 + BN + softmax -> g_depth/g_feat ===========
__global__ void __launch_bounds__(256, 4) k2_gemm2(void)
{
    __shared__ float hsh[HID*16];       // [c4][pix][4]
    __shared__ float vsh[16*VST];

    int blk = blockIdx.x, t = threadIdx.x;   // 352 = 2 * 176
    int b = blk / 176;
    int pixbase = (blk % 176) * 16;

    {
        int c4 = t >> 4, px = t & 15;
        ((float4*)hsh)[t] = ((const float4*)&g_h[(b*PIX + pixbase + px)*HID])[c4];
    }
    __syncthreads();

    int pix = t & 15, og = t >> 4;      // og 0..15
    {
        u64 acc[13];
#pragma unroll
        for (int k = 0; k < 13; k++) acc[k] = 0;
        bool has13 = (og < 6);
#pragma unroll
        for (int c4 = 0; c4 < 16; c4++) {
            ulonglong2 h2 = *(const ulonglong2*)&hsh[(c4*16 + pix)*4];
#pragma unroll
            for (int k = 0; k < 12; k++) {
                ulonglong2 wv = *(const ulonglong2*)&g_w2f[(og + 16*k)*HID + c4*4];
                fma2(acc[k], wv.x, h2.x);
                fma2(acc[k], wv.y, h2.y);
            }
            if (has13) {
                ulonglong2 wv = *(const ulonglong2*)&g_w2f[(192 + og)*HID + c4*4];
                fma2(acc[12], wv.x, h2.x);
                fma2(acc[12], wv.y, h2.y);
            }
        }
#pragma unroll
        for (int k = 0; k < 12; k++) {
            int o = og + 16*k;
            float2 p = unpack2(acc[k]);
            int s = (o < DEPTH) ? o : o + 2;
            vsh[pix*VST + s] = p.x + p.y + g_c2[o];
        }
        if (has13) {
            int o = 192 + og;
            float2 p = unpack2(acc[12]);
            vsh[pix*VST + o + 2] = p.x + p.y + g_c2[o];
        }
    }
    __syncthreads();

    // softmax over depth: 8 warps x 2 pixels, fast exp
    int lane = t & 31, warp = t >> 5;
#pragma unroll
    for (int j = 0; j < 2; j++) {
        int p = warp*2 + j;
        float a0 = vsh[p*VST + lane];
        float a1 = vsh[p*VST + lane + 32];
        float a2 = vsh[p*VST + lane + 64];
        float a3 = (lane + 96 < DEPTH) ? vsh[p*VST + lane + 96] : -INFINITY;
        float m = fmaxf(fmaxf(a0,a1), fmaxf(a2,a3));
#pragma unroll
        for (int s = 16; s; s >>= 1) m = fmaxf(m, __shfl_xor_sync(~0u, m, s));
        float e0 = __expf(a0 - m), e1 = __expf(a1 - m), e2 = __expf(a2 - m);
        float e3 = (lane + 96 < DEPTH) ? __expf(a3 - m) : 0.f;
        float sm = e0 + e1 + e2 + e3;
#pragma unroll
        for (int s = 16; s; s >>= 1) sm += __shfl_xor_sync(~0u, sm, s);
        float iv = 1.f / sm;
        vsh[p*VST + lane]      = e0*iv;
        vsh[p*VST + lane + 32] = e1*iv;
        vsh[p*VST + lane + 64] = e2*iv;
        if (lane + 96 < DEPTH) vsh[p*VST + lane + 96] = e3*iv;
    }
    __syncthreads();

    for (int i = t; i < 480; i += 256) {
        int px = i/30, j = i - px*30;
        *(float4*)&g_depth[(b*PIX + pixbase + px)*DPAD + j*4] = *(const float4*)&vsh[px*VST + j*4];
    }
    for (int i = t; i < 320; i += 256) {
        int px = i/20, q = i - px*20;
        *(float4*)&g_feat[(b*PIX + pixbase + px)*C_OUT + q*4] = *(const float4*)&vsh[px*VST + FOFF + q*4];
    }
}

// ---------------- geometry helpers ----------------
__device__ __forceinline__ int upper_bound_sh(const float* a, int n, float v)
{
    int lo = 0, hi = n;
    while (lo < hi) {
        int m = (lo + hi) >> 1;
        if (a[m] <= v) lo = m + 1; else hi = m;
    }
    return lo;
}

__device__ __forceinline__ int computeBin(int wi, int row, int d,
                                          const float* cam, const float* in4,
                                          const float* radE, const float* angE)
{
    float u = (wi == FW-1) ? (float)(IW-1) : (float)((double)wi * ((double)(IW-1)/(FW-1)));
    float v = (row == FH-1) ? (float)(IH-1) : (float)((double)row * ((double)(IH-1)/(FH-1)));
    float dv = 1.0f + 0.5f * (float)d;
    float pcx = (u - in4[2]) * dv / in4[0];
    float pcy = (v - in4[3]) * dv / in4[1];
    float pcz = dv;
    float xl = cam[0]*pcx + cam[1]*pcy + cam[2]*pcz + cam[9];
    float yl = cam[3]*pcx + cam[4]*pcy + cam[5]*pcz + cam[10];
    float r  = sqrtf(xl*xl + yl*yl);
    float th = atan2f(yl, xl);
    int ri = upper_bound_sh(radE, NR+1, r)  - 1;
    int ti = upper_bound_sh(angE, NT+1, th) - 1;
    if (ri < 0 || ri >= NR || ti < 0 || ti >= NT) return -1;
    return ri*NT + ti;
}

// theta bin only, at d-index 0, row 0 (valid when eq: row-independent)
__device__ __forceinline__ int computeTi(int wi, const float* cam, const float* in4,
                                         const float* angE)
{
    float u = (wi == FW-1) ? (float)(IW-1) : (float)((double)wi * ((double)(IW-1)/(FW-1)));
    float pcx = (u - in4[2]) / in4[0];
    float pcy = (0.f - in4[3]) / in4[1];
    float xl = cam[0]*pcx + cam[1]*pcy + cam[2] + cam[9];
    float yl = cam[3]*pcx + cam[4]*pcy + cam[5] + cam[10];
    float th = atan2f(yl, xl);
    int ti = upper_bound_sh(angE, NT+1, th) - 1;
    if (ti < 0 || ti >= NT) return -1;
    return ti;
}

// =========== K3: lift + polar scatter; block = (b, column, channel-half) ===========
// When the column exclusively owns its theta-bin (and geometry is depth/row-separable),
// results are written with plain stores; otherwise falls back to atomic REDs.
__global__ void __launch_bounds__(256, 4) k3_scatter(const float* __restrict__ rots,
                                                     const float* __restrict__ trans,
                                                     const float* __restrict__ intr,
                                                     float* __restrict__ out)
{
    __shared__ float dsh[32*DST];
    __shared__ float fsh[32*FST];
    __shared__ float wsum[DEPTH*32];
    __shared__ float radE[NR+1], angE[NT+4];
    __shared__ int   bins0[DEPTH], headBin[DEPTH], headS[DEPTH], headE[DEPTH];
    __shared__ int   tiArr[FW];
    __shared__ float cam[12], in4[4];
    __shared__ int   scal[4];   // [0]=nheads [1]=own [2]=eq

    int blk = blockIdx.x;             // 352 = 2b * 88wi * 2chalf
    int b = blk / 176;
    int rem = blk % 176;
    int wi = rem >> 1;
    int chalf = rem & 1;
    int t = threadIdx.x;

    for (int i = t; i <= NR; i += 256) radE[i] = g_radE[i];
    for (int i = t; i <= NT; i += 256) angE[i] = g_angE[i];
    if (t < 9) cam[t] = rots[b*9 + t];
    if (t < 3) cam[9+t] = trans[b*3 + t];
    if (t == 0) {
        in4[0] = intr[b*9 + 0]; in4[1] = intr[b*9 + 4];
        in4[2] = intr[b*9 + 2]; in4[3] = intr[b*9 + 5];
        scal[0] = 0;
        scal[2] = (rots[b*9 + 1] == 0.f && rots[b*9 + 4] == 0.f) ? 1 : 0;
        // depth-separable theta + monotone r requires zero xy-translation
        scal[3] = (trans[b*3] == 0.f && trans[b*3 + 1] == 0.f) ? 1 : 0;
    }

    // stage depth (32 rows x 30 f4 -> stride-121 scalars) and feat half (32 x 10 f4)
    for (int i = t; i < 960; i += 256) {
        int row = i/30, j = i - row*30;
        float4 v = *(const float4*)&g_depth[(b*PIX + row*FW + wi)*DPAD + j*4];
        float* dp = &dsh[row*DST + j*4];
        dp[0] = v.x; dp[1] = v.y; dp[2] = v.z; dp[3] = v.w;
    }
    for (int i = t; i < 320; i += 256) {
        int row = i/10, q = i - row*10;
        *(float4*)&fsh[row*FST + q*4] =
            *(const float4*)&g_feat[(b*PIX + row*FW + wi)*C_OUT + chalf*40 + q*4];
    }
    __syncthreads();

    int eq = scal[2];
    float* outb = out + b*C_OUT*NRT + (chalf*40)*NRT;

    if (eq) {
        // bins for row 0 (row-independent); theta table for ownership
        if (t < DEPTH) bins0[t] = computeBin(wi, 0, t, cam, in4, radE, angE);
        if (t >= 128 && t < 128 + FW) tiArr[t - 128] = computeTi(t - 128, cam, in4, angE);
        __syncthreads();
        if (t == 0) {
            int own = scal[3];
            int myti = tiArr[wi];
            if (myti < 0) own = 0;
            else {
                for (int w = 0; w < FW; w++)
                    if (w != wi && tiArr[w] == myti) { own = 0; break; }
            }
            scal[1] = own;
        }
        // run-compress bins
        if (t < DEPTH) {
            int bn = bins0[t];
            if (bn >= 0 && (t == 0 || bins0[t-1] != bn)) {
                int k = t + 1;
                while (k < DEPTH && bins0[k] == bn) k++;
                int s = atomicAdd(&scal[0], 1);
                headBin[s] = bn; headS[s] = t; headE[s] = k;
            }
        }
        __syncthreads();
        int nh = scal[0];
        int own = scal[1];
        for (int i = t; i < nh*32; i += 256) {
            int h = i >> 5, row = i & 31;
            float s = 0.f;
            for (int d = headS[h]; d < headE[h]; d++) s += dsh[row*DST + d];
            wsum[h*32 + row] = s;
        }
        __syncthreads();
        int npair = (nh + 1) >> 1;
        for (int i = t; i < npair*10; i += 256) {
            int hp = i/10, q = i - hp*10;
            int h0 = hp*2, h1 = h0 + 1;
            bool two = (h1 < nh);
            float4 A = make_float4(0.f,0.f,0.f,0.f);
            float4 Bv = make_float4(0.f,0.f,0.f,0.f);
#pragma unroll 4
            for (int row = 0; row < 32; row++) {
                float4 f = *(const float4*)&fsh[row*FST + q*4];
                float w0 = wsum[h0*32 + row];
                A.x += w0*f.x; A.y += w0*f.y; A.z += w0*f.z; A.w += w0*f.w;
                if (two) {
                    float w1 = wsum[h1*32 + row];
                    Bv.x += w1*f.x; Bv.y += w1*f.y; Bv.z += w1*f.z; Bv.w += w1*f.w;
                }
            }
            float* p0 = outb + (q*4)*NRT + headBin[h0];
            float* p1 = two ? (outb + (q*4)*NRT + headBin[h1]) : 0;
            if (own) {
                p0[0] = A.x; p0[NRT] = A.y; p0[2*NRT] = A.z; p0[3*NRT] = A.w;
                if (two) { p1[0] = Bv.x; p1[NRT] = Bv.y; p1[2*NRT] = Bv.z; p1[3*NRT] = Bv.w; }
            } else {
                redadd(p0, A.x); redadd(p0+NRT, A.y); redadd(p0+2*NRT, A.z); redadd(p0+3*NRT, A.w);
                if (two) { redadd(p1, Bv.x); redadd(p1+NRT, Bv.y); redadd(p1+2*NRT, Bv.z); redadd(p1+3*NRT, Bv.w); }
            }
        }
    } else {
        // generic fallback: per-row scatter with REDs
        for (int row = 0; row < 32; row++) {
            __syncthreads();
            if (t == 0) scal[0] = 0;
            __syncthreads();
            if (t < DEPTH) bins0[t] = computeBin(wi, row, t, cam, in4, radE, angE);
            __syncthreads();
            if (t < DEPTH) {
                int bn = bins0[t];
                if (bn >= 0 && (t == 0 || bins0[t-1] != bn)) {
                    int k = t + 1;
                    while (k < DEPTH && bins0[k] == bn) k++;
                    float s = 0.f;
                    for (int d = t; d < k; d++) s += dsh[row*DST + d];
                    int sN = atomicAdd(&scal[0], 1);
                    headBin[sN] = bn;
                    headS[sN] = __float_as_int(s);
                }
            }
            __syncthreads();
            int nh = scal[0];
            for (int i = t; i < nh*10; i += 256) {
                int h = i/10, q = i - h*10;
                float w = __int_as_float(headS[h]);
                const float* f = &fsh[row*FST + q*4];
                float* p0 = outb + (q*4)*NRT + headBin[h];
                redadd(p0,          w*f[0]);
                redadd(p0 +   NRT,  w*f[1]);
                redadd(p0 + 2*NRT,  w*f[2]);
                redadd(p0 + 3*NRT,  w*f[3]);
            }
        }
    }
}

// ---------------- launch ----------------
extern "C" void kernel_launch(void* const* d_in, const int* in_sizes, int n_in,
                              void* d_out, int out_size)
{
    const float* x     = (const float*)d_in[0];
    const float* rots  = (const float*)d_in[1];
    const float* trans = (const float*)d_in[2];
    const float* intr  = (const float*)d_in[3];
    const float* w1    = (const float*)d_in[4];
    const float* b1    = (const float*)d_in[5];
    const float* g1    = (const float*)d_in[6];
    const float* be1   = (const float*)d_in[7];
    const float* m1    = (const float*)d_in[8];
    const float* v1    = (const float*)d_in[9];
    const float* w2    = (const float*)d_in[10];
    const float* b2    = (const float*)d_in[11];
    const float* g2    = (const float*)d_in[12];
    const float* be2   = (const float*)d_in[13];
    const float* m2    = (const float*)d_in[14];
    const float* v2    = (const float*)d_in[15];
    float* out = (float*)d_out;

    k1_gemm1<<<489, 256>>>(x, w1, b1, g1, be1, m1, v1,
                           w2, b2, g2, be2, m2, v2, out);
    k2_gemm2<<<352, 256>>>();
    k3_scatter<<<352, 256>>>(rots, trans, intr, out);
}

// round 13
// speedup vs baseline: 1.0768x; 1.0768x over previous
#include <cuda_runtime.h>
#include <math.h>

#define IH 256
#define IW 704
#define FH 32
#define FW 88
#define PIX (FH*FW)          // 2816
#define BATCH 2
#define C_IN 256
#define HID 64
#define DEPTH 118
#define C_OUT 80
#define OUT2 (DEPTH + C_OUT) // 198
#define NR 128
#define NT 256
#define NRT (NR*NT)          // 32768
#define PI_D 3.141592653589793
#define VST 204              // vsh row stride (feat at +120)
#define FOFF 120
#define HST 68               // hsh row stride

typedef unsigned long long u64;

// ---------------- device scratch ----------------
__device__ float g_h[BATCH*PIX*HID];             // [b][pix][hid]
__device__ __align__(16) float g_w2f[OUT2*HID];  // BN-folded w2
__device__ float g_c2[OUT2];
__device__ float g_radE[NR+1];
__device__ float g_angE[NT+1];

// ---------------- f32x2 helpers ----------------
__device__ __forceinline__ void fma2(u64& d, u64 a, u64 b) {
    asm("fma.rn.f32x2 %0, %1, %2, %3;" : "=l"(d) : "l"(a), "l"(b), "l"(d));
}
__device__ __forceinline__ float2 unpack2(u64 v) {
    float2 r; asm("mov.b64 {%0,%1}, %2;" : "=f"(r.x), "=f"(r.y) : "l"(v)); return r;
}
__device__ __forceinline__ void redadd(float* p, float v) {
    asm volatile("red.global.add.f32 [%0], %1;" :: "l"(p), "f"(v) : "memory");
}

// ---------------- K1: GEMM1 (double-buffered) + zero d_out + prep tables ----------------
// blocks 0..351: GEMM (16 pixels each). 352..479: zero d_out. 480: edges+c2. 481..488: fold w2.
__global__ void __launch_bounds__(256) k1_gemm1(const float* __restrict__ x,
                                                const float* __restrict__ w1,
                                                const float* __restrict__ b1,
                                                const float* __restrict__ g1,
                                                const float* __restrict__ be1,
                                                const float* __restrict__ m1,
                                                const float* __restrict__ v1,
                                                const float* __restrict__ w2,
                                                const float* __restrict__ b2,
                                                const float* __restrict__ g2,
                                                const float* __restrict__ be2,
                                                const float* __restrict__ m2,
                                                const float* __restrict__ v2,
                                                float* __restrict__ outz)
{
    __shared__ float xs[2][64*16];   // [c][pix]
    __shared__ float ws[2][64*65];   // [c][o], stride 65

    int blk = blockIdx.x, t = threadIdx.x;

    if (blk >= 352) {
        if (blk < 480) {
            int base = (blk - 352) * 10240;
            float4 z = make_float4(0.f,0.f,0.f,0.f);
#pragma unroll 4
            for (int i = t; i < 10240; i += 256)
                ((float4*)outz)[base + i] = z;
        } else if (blk == 480) {
            if (t <= NR) {
                double tt = (double)t * (1.0/128.0);
                g_radE[t] = (float)(1.0 + pow(tt, 1.5) * 59.0);
            }
            for (int i = t; i <= NT; i += 256) {
                double a = (i == NT) ? (PI_D*0.5) : (-PI_D*0.5 + (double)i * (PI_D/256.0));
                g_angE[i] = (float)a;
            }
            if (t < OUT2) {
                float inv = g2[t] / sqrtf(v2[t] + 1e-5f);
                g_c2[t] = b2[t]*inv + be2[t] - m2[t]*inv;
            }
        } else {
            int base = (blk - 481) * 396;
            for (int j = base + t; j < base + 396; j += 256) {
                int o = j >> 4;
                float inv = g2[o] / sqrtf(v2[o] + 1e-5f);
                float4 w = ((const float4*)w2)[j];
                w.x *= inv; w.y *= inv; w.z *= inv; w.w *= inv;
                ((float4*)g_w2f)[j] = w;
            }
        }
        return;
    }

    int b = blk / 176;
    int pixbase = (blk % 176) * 16;
    int o  = t & 63;
    int pg = t >> 6;
    int cx_ = t >> 2, px4 = t & 3;          // x staging coords

    float4 xreg;
    float4 wreg[4];

    // prologue: stage cc=0
    xreg = ((const float4*)(x + (b*C_IN + cx_)*PIX + pixbase))[px4];
#pragma unroll
    for (int i = 0; i < 4; i++) {
        int j = t + i*256; int oo = j >> 4, k4 = j & 15;
        wreg[i] = *(const float4*)(w1 + oo*C_IN + k4*4);
    }
    ((float4*)xs[0])[t] = xreg;
#pragma unroll
    for (int i = 0; i < 4; i++) {
        int j = t + i*256; int oo = j >> 4, k4 = j & 15;
        ws[0][(k4*4+0)*65 + oo] = wreg[i].x;
        ws[0][(k4*4+1)*65 + oo] = wreg[i].y;
        ws[0][(k4*4+2)*65 + oo] = wreg[i].z;
        ws[0][(k4*4+3)*65 + oo] = wreg[i].w;
    }
    __syncthreads();

    float4 acc = make_float4(0.f,0.f,0.f,0.f);

#pragma unroll
    for (int cc = 0; cc < 4; cc++) {
        int buf = cc & 1;
        if (cc < 3) {
            // prefetch next stage into registers (overlaps compute below)
            xreg = ((const float4*)(x + (b*C_IN + (cc+1)*64 + cx_)*PIX + pixbase))[px4];
#pragma unroll
            for (int i = 0; i < 4; i++) {
                int j = t + i*256; int oo = j >> 4, k4 = j & 15;
                wreg[i] = *(const float4*)(w1 + oo*C_IN + (cc+1)*64 + k4*4);
            }
        }
#pragma unroll 8
        for (int cl = 0; cl < 64; cl++) {
            float w = ws[buf][cl*65 + o];
            float4 xv = *(const float4*)&xs[buf][cl*16 + pg*4];
            acc.x += w*xv.x; acc.y += w*xv.y; acc.z += w*xv.z; acc.w += w*xv.w;
        }
        if (cc < 3) {
            ((float4*)xs[1-buf])[t] = xreg;
#pragma unroll
            for (int i = 0; i < 4; i++) {
                int j = t + i*256; int oo = j >> 4, k4 = j & 15;
                ws[1-buf][(k4*4+0)*65 + oo] = wreg[i].x;
                ws[1-buf][(k4*4+1)*65 + oo] = wreg[i].y;
                ws[1-buf][(k4*4+2)*65 + oo] = wreg[i].z;
                ws[1-buf][(k4*4+3)*65 + oo] = wreg[i].w;
            }
            __syncthreads();
        }
    }
    float inv  = g1[o] / sqrtf(v1[o] + 1e-5f);
    float bias = b1[o]*inv + be1[o] - m1[o]*inv;
    int pbase = b*PIX + pixbase + pg*4;
    g_h[(pbase+0)*HID + o] = fmaxf(acc.x*inv + bias, 0.f);
    g_h[(pbase+1)*HID + o] = fmaxf(acc.y*inv + bias, 0.f);
    g_h[(pbase+2)*HID + o] = fmaxf(acc.z*inv + bias, 0.f);
    g_h[(pbase+3)*HID + o] = fmaxf(acc.w*inv + bias, 0.f);
}

// ---------------- geometry helpers ----------------
__device__ __forceinline__ int upper_bound_sh(const float* a, int n, float v)
{
    int lo = 0, hi = n;
    while (lo < hi) {
        int m = (lo + hi) >> 1;
        if (a[m] <= v) lo = m + 1; else hi = m;
    }
    return lo;
}

__device__ __forceinline__ int computeBin(int wi, int row, int d,
                                          const float* cam, const float* in4,
                                          const float* radE, const float* angE)
{
    float u = (wi == FW-1) ? (float)(IW-1) : (float)((double)wi * ((double)(IW-1)/(FW-1)));
    float v = (row == FH-1) ? (float)(IH-1) : (float)((double)row * ((double)(IH-1)/(FH-1)));
    float dv = 1.0f + 0.5f * (float)d;
    float pcx = (u - in4[2]) * dv / in4[0];
    float pcy = (v - in4[3]) * dv / in4[1];
    float pcz = dv;
    float xl = cam[0]*pcx + cam[1]*pcy + cam[2]*pcz + cam[9];
    float yl = cam[3]*pcx + cam[4]*pcy + cam[5]*pcz + cam[10];
    float r  = sqrtf(xl*xl + yl*yl);
    float th = atan2f(yl, xl);
    int ri = upper_bound_sh(radE, NR+1, r)  - 1;
    int ti = upper_bound_sh(angE, NT+1, th) - 1;
    if (ri < 0 || ri >= NR || ti < 0 || ti >= NT) return -1;
    return ri*NT + ti;
}

// theta bin at row 0, d=1 (d/row-invariant when eq && trans.xy==0)
__device__ __forceinline__ int computeTi(int wi, const float* cam, const float* in4,
                                         const float* angE)
{
    float u = (wi == FW-1) ? (float)(IW-1) : (float)((double)wi * ((double)(IW-1)/(FW-1)));
    float pcx = (u - in4[2]) / in4[0];
    float pcy = (0.f - in4[3]) / in4[1];
    float xl = cam[0]*pcx + cam[1]*pcy + cam[2] + cam[9];
    float yl = cam[3]*pcx + cam[4]*pcy + cam[5] + cam[10];
    float th = atan2f(yl, xl);
    int ti = upper_bound_sh(angE, NT+1, th) - 1;
    if (ti < 0 || ti >= NT) return -1;
    return ti;
}

// dynamic smem layout (floats)
#define SM_W2S   0                 // 12672
#define SM_C2S   12672             // 200
#define SM_VSH   12872             // 32*204 = 6528
#define SM_UNI   19400             // hsh 32*68=2176 / wsum 118*32=3776
#define SM_RADE  23176             // 132
#define SM_ANGE  23308             // 260
#define SM_BINS  23568             // 120 (int)
#define SM_HB    23688             // 120
#define SM_HS    23808             // 120
#define SM_HE    23928             // 120
#define SM_CAM   24048             // 12
#define SM_IN4   24060             // 4
#define SM_TIA   24064             // 88 (int)
#define SM_SCAL  24152             // 4 ints: [0]=nheads [1]=own [2]=eq [3]=tz
#define K23_FLOATS 24156
#define K23_SMEM (K23_FLOATS*4)

// ---------------- K23: GEMM2 + BN + softmax + lift + scatter; block = column ----------------
__global__ void __launch_bounds__(512, 2) k23_fused(const float* __restrict__ rots,
                                                    const float* __restrict__ trans,
                                                    const float* __restrict__ intr,
                                                    float* __restrict__ out)
{
    extern __shared__ float smem[];
    float* w2s  = smem + SM_W2S;
    float* c2s  = smem + SM_C2S;
    float* vsh  = smem + SM_VSH;
    float* uni  = smem + SM_UNI;
    float* radE = smem + SM_RADE;
    float* angE = smem + SM_ANGE;
    int*   bins0   = (int*)(smem + SM_BINS);
    int*   headBin = (int*)(smem + SM_HB);
    int*   headS   = (int*)(smem + SM_HS);
    int*   headE   = (int*)(smem + SM_HE);
    float* cam  = smem + SM_CAM;
    float* in4  = smem + SM_IN4;
    int*   tiArr = (int*)(smem + SM_TIA);
    int*   scal = (int*)(smem + SM_SCAL);

    int blk = blockIdx.x;             // 176 = 2 batches * 88 columns
    int b = blk / FW, wi = blk % FW;
    int t = threadIdx.x;

    // stage precomputed tables
    for (int j = t; j < 3168; j += 512)
        ((float4*)w2s)[j] = ((const float4*)g_w2f)[j];
    if (t < OUT2) c2s[t] = g_c2[t];
    for (int i = t; i <= NR; i += 512) radE[i] = g_radE[i];
    for (int i = t; i <= NT; i += 512) angE[i] = g_angE[i];
    if (t < 9) cam[t] = rots[b*9 + t];
    if (t < 3) cam[9+t] = trans[b*3 + t];
    if (t == 0) {
        in4[0] = intr[b*9 + 0]; in4[1] = intr[b*9 + 4];
        in4[2] = intr[b*9 + 2]; in4[3] = intr[b*9 + 5];
        scal[0] = 0;
        int eq = (rots[b*9 + 1] == 0.f && rots[b*9 + 4] == 0.f) ? 1 : 0;
        int tz = (trans[b*3] == 0.f && trans[b*3 + 1] == 0.f) ? 1 : 0;
        scal[2] = eq;
        scal[1] = eq && tz;       // ownership candidate; refined below
    }

    // load hidden for 32 rows: hsh[row*HST + c]
    float* hsh = uni;
    {
        int row = t >> 4, c4 = t & 15;
        ((float4*)&hsh[row*HST])[c4] = ((const float4*)&g_h[(b*PIX + row*FW + wi)*HID])[c4];
    }
    __syncthreads();

    // bins for row 0 + theta table (overlap GEMM2 on MUFU/ALU pipes)
    if (t < DEPTH) bins0[t] = computeBin(wi, 0, t, cam, in4, radE, angE);
    if (t >= 128 && t < 128 + FW) tiArr[t - 128] = computeTi(t - 128, cam, in4, angE);

    // GEMM2: 32 pixels x 198 outputs, f32x2
    int pix = t & 31, og = t >> 5;     // og 0..15 (warp-uniform -> broadcast LDS)
    {
        u64 acc[13];
#pragma unroll
        for (int k = 0; k < 13; k++) acc[k] = 0;
        bool has13 = (og < 6);
#pragma unroll
        for (int c4 = 0; c4 < 16; c4++) {
            ulonglong2 h2 = *(const ulonglong2*)&hsh[pix*HST + c4*4];
#pragma unroll
            for (int k = 0; k < 12; k++) {
                ulonglong2 wv = *(const ulonglong2*)&w2s[(og + 16*k)*HID + c4*4];
                fma2(acc[k], wv.x, h2.x);
                fma2(acc[k], wv.y, h2.y);
            }
            if (has13) {
                ulonglong2 wv = *(const ulonglong2*)&w2s[(192 + og)*HID + c4*4];
                fma2(acc[12], wv.x, h2.x);
                fma2(acc[12], wv.y, h2.y);
            }
        }
#pragma unroll
        for (int k = 0; k < 12; k++) {
            int o = og + 16*k;
            float2 p = unpack2(acc[k]);
            int s = (o < DEPTH) ? o : o + 2;
            vsh[pix*VST + s] = p.x + p.y + c2s[o];
        }
        if (has13) {
            int o = 192 + og;
            float2 p = unpack2(acc[12]);
            vsh[pix*VST + o + 2] = p.x + p.y + c2s[o];
        }
    }
    __syncthreads();

    // ownership refinement (cheap, parallel; benign 0-races)
    if (t < FW && t != wi && tiArr[t] == tiArr[wi]) scal[1] = 0;
    if (t == wi && tiArr[wi] < 0)                   scal[1] = 0;
    if (t < DEPTH && bins0[t] >= 0 && (bins0[t] & (NT-1)) != tiArr[wi]) scal[1] = 0;

    // softmax over depth: 16 warps x 2 pixels, fast exp
    int lane = t & 31, warp = t >> 5;
#pragma unroll
    for (int j = 0; j < 2; j++) {
        int p = warp*2 + j;
        float a0 = vsh[p*VST + lane];
        float a1 = vsh[p*VST + lane + 32];
        float a2 = vsh[p*VST + lane + 64];
        float a3 = (lane + 96 < DEPTH) ? vsh[p*VST + lane + 96] : -INFINITY;
        float m = fmaxf(fmaxf(a0,a1), fmaxf(a2,a3));
#pragma unroll
        for (int s = 16; s; s >>= 1) m = fmaxf(m, __shfl_xor_sync(~0u, m, s));
        float e0 = __expf(a0 - m), e1 = __expf(a1 - m), e2 = __expf(a2 - m);
        float e3 = (lane + 96 < DEPTH) ? __expf(a3 - m) : 0.f;
        float sm = e0 + e1 + e2 + e3;
#pragma unroll
        for (int s = 16; s; s >>= 1) sm += __shfl_xor_sync(~0u, sm, s);
        float iv = 1.f / sm;
        vsh[p*VST + lane]      = e0*iv;
        vsh[p*VST + lane + 32] = e1*iv;
        vsh[p*VST + lane + 64] = e2*iv;
        if (lane + 96 < DEPTH) vsh[p*VST + lane + 96] = e3*iv;
    }
    __syncthreads();

    float* outb = out + b*C_OUT*NRT;

    if (scal[2]) {
        // run-compress row0 bins (row-independent)
        if (t < DEPTH) {
            int bn = bins0[t];
            if (bn >= 0 && (t == 0 || bins0[t-1] != bn)) {
                int k = t + 1;
                while (k < DEPTH && bins0[k] == bn) k++;
                int s = atomicAdd(&scal[0], 1);
                headBin[s] = bn; headS[s] = t; headE[s] = k;
            }
        }
        __syncthreads();
        int nh = scal[0];
        int own = scal[1];
        float* wsum = uni;   // hsh dead
        for (int i = t; i < nh*32; i += 512) {
            int h = i >> 5, row = i & 31;
            float s = 0.f;
            for (int d = headS[h]; d < headE[h]; d++) s += vsh[row*VST + d];
            wsum[h*32 + row] = s;
        }
        __syncthreads();
        int npair = (nh + 1) >> 1;
        for (int i = t; i < npair*20; i += 512) {
            int hp = i/20, q = i - hp*20;
            int h0 = hp*2, h1 = h0 + 1;
            bool two = (h1 < nh);
            float4 A = make_float4(0.f,0.f,0.f,0.f);
            float4 Bv = make_float4(0.f,0.f,0.f,0.f);
#pragma unroll 4
            for (int row = 0; row < 32; row++) {
                float4 f = *(const float4*)&vsh[row*VST + FOFF + q*4];
                float w0 = wsum[h0*32 + row];
                A.x += w0*f.x; A.y += w0*f.y; A.z += w0*f.z; A.w += w0*f.w;
                if (two) {
                    float w1 = wsum[h1*32 + row];
                    Bv.x += w1*f.x; Bv.y += w1*f.y; Bv.z += w1*f.z; Bv.w += w1*f.w;
                }
            }
            float* p0 = outb + (q*4)*NRT + headBin[h0];
            float* p1 = two ? (outb + (q*4)*NRT + headBin[h1]) : (float*)0;
            if (own) {
                p0[0] = A.x; p0[NRT] = A.y; p0[2*NRT] = A.z; p0[3*NRT] = A.w;
                if (two) { p1[0] = Bv.x; p1[NRT] = Bv.y; p1[2*NRT] = Bv.z; p1[3*NRT] = Bv.w; }
            } else {
                redadd(p0,          A.x);
                redadd(p0 +   NRT,  A.y);
                redadd(p0 + 2*NRT,  A.z);
                redadd(p0 + 3*NRT,  A.w);
                if (two) {
                    redadd(p1,          Bv.x);
                    redadd(p1 +   NRT,  Bv.y);
                    redadd(p1 + 2*NRT,  Bv.z);
                    redadd(p1 + 3*NRT,  Bv.w);
                }
            }
        }
    } else {
        // generic fallback: per-row scatter with REDs
        for (int row = 0; row < 32; row++) {
            __syncthreads();
            if (t == 0) scal[0] = 0;
            __syncthreads();
            if (t < DEPTH) bins0[t] = computeBin(wi, row, t, cam, in4, radE, angE);
            __syncthreads();
            if (t < DEPTH) {
                int bn = bins0[t];
                if (bn >= 0 && (t == 0 || bins0[t-1] != bn)) {
                    int k = t + 1;
                    while (k < DEPTH && bins0[k] == bn) k++;
                    float s = 0.f;
                    for (int d = t; d < k; d++) s += vsh[row*VST + d];
                    int sN = atomicAdd(&scal[0], 1);
                    headBin[sN] = bn;
                    headS[sN] = __float_as_int(s);
                }
            }
            __syncthreads();
            int nh = scal[0];
            for (int i = t; i < nh*20; i += 512) {
                int h = i/20, q = i - h*20;
                float w = __int_as_float(headS[h]);
                const float* f = &vsh[row*VST + FOFF + q*4];
                float* p0 = outb + (q*4)*NRT + headBin[h];
                redadd(p0,          w*f[0]);
                redadd(p0 +   NRT,  w*f[1]);
                redadd(p0 + 2*NRT,  w*f[2]);
                redadd(p0 + 3*NRT,  w*f[3]);
            }
        }
    }
}

// ---------------- launch ----------------
extern "C" void kernel_launch(void* const* d_in, const int* in_sizes, int n_in,
                              void* d_out, int out_size)
{
    const float* x     = (const float*)d_in[0];
    const float* rots  = (const float*)d_in[1];
    const float* trans = (const float*)d_in[2];
    const float* intr  = (const float*)d_in[3];
    const float* w1    = (const float*)d_in[4];
    const float* b1    = (const float*)d_in[5];
    const float* g1    = (const float*)d_in[6];
    const float* be1   = (const float*)d_in[7];
    const float* m1    = (const float*)d_in[8];
    const float* v1    = (const float*)d_in[9];
    const float* w2    = (const float*)d_in[10];
    const float* b2    = (const float*)d_in[11];
    const float* g2    = (const float*)d_in[12];
    const float* be2   = (const float*)d_in[13];
    const float* m2    = (const float*)d_in[14];
    const float* v2    = (const float*)d_in[15];
    float* out = (float*)d_out;

    static int configured = 0;
    if (!configured) {
        cudaFuncSetAttribute(k23_fused, cudaFuncAttributeMaxDynamicSharedMemorySize, K23_SMEM);
        configured = 1;
    }

    k1_gemm1<<<489, 256>>>(x, w1, b1, g1, be1, m1, v1,
                           w2, b2, g2, be2, m2, v2, out);
    k23_fused<<<176, 512, K23_SMEM>>>(rots, trans, intr, out);
}

// round 15
// speedup vs baseline: 1.1720x; 1.0884x over previous
#include <cuda_runtime.h>
#include <math.h>

#define IH 256
#define IW 704
#define FH 32
#define FW 88
#define PIX (FH*FW)          // 2816
#define BATCH 2
#define C_IN 256
#define HID 64
#define DEPTH 118
#define C_OUT 80
#define OUT2 (DEPTH + C_OUT) // 198
#define NR 128
#define NT 256
#define NRT (NR*NT)          // 32768
#define PI_D 3.141592653589793
#define VST 204              // vsh row stride (feat at +120)
#define FOFF 120
#define HST 68               // hsh row stride

typedef unsigned long long u64;

// ---------------- device scratch ----------------
__device__ float g_h[BATCH*PIX*HID];             // [b][pix][hid]
__device__ __align__(16) float g_w2f[OUT2*HID];  // BN-folded w2
__device__ float g_c2[OUT2];
__device__ float g_radE[NR+1];
__device__ float g_angE[NT+1];

// ---------------- f32x2 helpers ----------------
__device__ __forceinline__ void fma2(u64& d, u64 a, u64 b) {
    asm("fma.rn.f32x2 %0, %1, %2, %3;" : "=l"(d) : "l"(a), "l"(b), "l"(d));
}
__device__ __forceinline__ float2 unpack2(u64 v) {
    float2 r; asm("mov.b64 {%0,%1}, %2;" : "=f"(r.x), "=f"(r.y) : "l"(v)); return r;
}
__device__ __forceinline__ void redadd(float* p, float v) {
    asm volatile("red.global.add.f32 [%0], %1;" :: "l"(p), "f"(v) : "memory");
}

// ---------------- K1: GEMM1 + zero d_out + precompute tables / folded w2 (R6 version) ------
__global__ void __launch_bounds__(256) k1_gemm1(const float* __restrict__ x,
                                                const float* __restrict__ w1,
                                                const float* __restrict__ b1,
                                                const float* __restrict__ g1,
                                                const float* __restrict__ be1,
                                                const float* __restrict__ m1,
                                                const float* __restrict__ v1,
                                                const float* __restrict__ w2,
                                                const float* __restrict__ b2,
                                                const float* __restrict__ g2,
                                                const float* __restrict__ be2,
                                                const float* __restrict__ m2,
                                                const float* __restrict__ v2,
                                                float* __restrict__ outz)
{
    __shared__ float xs[64*16];      // [c][pix]
    __shared__ float ws[64*65];      // [c][o], stride 65

    int blk = blockIdx.x, t = threadIdx.x;

    if (blk >= 352) {
        if (blk < 480) {
            int base = (blk - 352) * 10240;
            float4 z = make_float4(0.f,0.f,0.f,0.f);
#pragma unroll 4
            for (int i = t; i < 10240; i += 256)
                ((float4*)outz)[base + i] = z;
        } else if (blk == 480) {
            if (t <= NR) {
                double tt = (double)t * (1.0/128.0);
                g_radE[t] = (float)(1.0 + pow(tt, 1.5) * 59.0);
            }
            for (int i = t; i <= NT; i += 256) {
                double a = (i == NT) ? (PI_D*0.5) : (-PI_D*0.5 + (double)i * (PI_D/256.0));
                g_angE[i] = (float)a;
            }
            if (t < OUT2) {
                float inv = g2[t] / sqrtf(v2[t] + 1e-5f);
                g_c2[t] = b2[t]*inv + be2[t] - m2[t]*inv;
            }
        } else {
            int base = (blk - 481) * 396;
            for (int j = base + t; j < base + 396; j += 256) {
                int o = j >> 4;
                float inv = g2[o] / sqrtf(v2[o] + 1e-5f);
                float4 w = ((const float4*)w2)[j];
                w.x *= inv; w.y *= inv; w.z *= inv; w.w *= inv;
                ((float4*)g_w2f)[j] = w;
            }
        }
        return;
    }

    int b = blk / 176;
    int pixbase = (blk % 176) * 16;
    int o  = t & 63;
    int pg = t >> 6;

    float4 acc = make_float4(0.f,0.f,0.f,0.f);

    for (int cc = 0; cc < 4; cc++) {
        __syncthreads();
        {
            int c = t >> 2, p4 = t & 3;
            ((float4*)xs)[t] = ((const float4*)(x + (b*C_IN + cc*64 + c)*PIX + pixbase))[p4];
        }
#pragma unroll
        for (int i = 0; i < 4; i++) {
            int j = t + i*256;
            int oo = j >> 4, k4 = j & 15;
            float4 w = *(const float4*)(w1 + oo*C_IN + cc*64 + k4*4);
            ws[(k4*4+0)*65 + oo] = w.x;
            ws[(k4*4+1)*65 + oo] = w.y;
            ws[(k4*4+2)*65 + oo] = w.z;
            ws[(k4*4+3)*65 + oo] = w.w;
        }
        __syncthreads();
#pragma unroll 8
        for (int cl = 0; cl < 64; cl++) {
            float w = ws[cl*65 + o];
            float4 xv = *(const float4*)&xs[cl*16 + pg*4];
            acc.x += w*xv.x; acc.y += w*xv.y; acc.z += w*xv.z; acc.w += w*xv.w;
        }
    }
    float inv  = g1[o] / sqrtf(v1[o] + 1e-5f);
    float bias = b1[o]*inv + be1[o] - m1[o]*inv;
    int pbase = b*PIX + pixbase + pg*4;
    g_h[(pbase+0)*HID + o] = fmaxf(acc.x*inv + bias, 0.f);
    g_h[(pbase+1)*HID + o] = fmaxf(acc.y*inv + bias, 0.f);
    g_h[(pbase+2)*HID + o] = fmaxf(acc.z*inv + bias, 0.f);
    g_h[(pbase+3)*HID + o] = fmaxf(acc.w*inv + bias, 0.f);
}

// ---------------- geometry helpers ----------------
__device__ __forceinline__ int upper_bound_sh(const float* a, int n, float v)
{
    int lo = 0, hi = n;
    while (lo < hi) {
        int m = (lo + hi) >> 1;
        if (a[m] <= v) lo = m + 1; else hi = m;
    }
    return lo;
}

__device__ __forceinline__ int computeBin(int wi, int row, int d,
                                          const float* cam, const float* in4,
                                          const float* radE, const float* angE)
{
    float u = (wi == FW-1) ? (float)(IW-1) : (float)((double)wi * ((double)(IW-1)/(FW-1)));
    float v = (row == FH-1) ? (float)(IH-1) : (float)((double)row * ((double)(IH-1)/(FH-1)));
    float dv = 1.0f + 0.5f * (float)d;
    float pcx = (u - in4[2]) * dv / in4[0];
    float pcy = (v - in4[3]) * dv / in4[1];
    float pcz = dv;
    float xl = cam[0]*pcx + cam[1]*pcy + cam[2]*pcz + cam[9];
    float yl = cam[3]*pcx + cam[4]*pcy + cam[5]*pcz + cam[10];
    float r  = sqrtf(xl*xl + yl*yl);
    float th = atan2f(yl, xl);
    int ri = upper_bound_sh(radE, NR+1, r)  - 1;
    int ti = upper_bound_sh(angE, NT+1, th) - 1;
    if (ri < 0 || ri >= NR || ti < 0 || ti >= NT) return -1;
    return ri*NT + ti;
}

// dynamic smem layout (floats)
#define SM_W2S   0                 // 12672
#define SM_C2S   12672             // 200
#define SM_VSH   12872             // 32*204 = 6528
#define SM_UNI   19400             // hsh 32*68=2176 / wsum 118*32=3776
#define SM_RADE  23176             // 132
#define SM_ANGE  23308             // 260
#define SM_BINS  23568             // 120 (int)
#define SM_HB    23688             // 120
#define SM_HS    23808             // 120
#define SM_HE    23928             // 120
#define SM_CAM   24048             // 12
#define SM_IN4   24060             // 4
#define SM_SCAL  24064             // 4 ints
#define K23_FLOATS 24068
#define K23_SMEM (K23_FLOATS*4)

// ---------------- K23: GEMM2 + BN + softmax + lift + scatter; block = column, 1024 thr ------
__global__ void __launch_bounds__(1024, 1) k23_fused(const float* __restrict__ rots,
                                                     const float* __restrict__ trans,
                                                     const float* __restrict__ intr,
                                                     float* __restrict__ out)
{
    extern __shared__ float smem[];
    float* w2s  = smem + SM_W2S;
    float* c2s  = smem + SM_C2S;
    float* vsh  = smem + SM_VSH;
    float* uni  = smem + SM_UNI;
    float* radE = smem + SM_RADE;
    float* angE = smem + SM_ANGE;
    int*   bins0   = (int*)(smem + SM_BINS);
    int*   headBin = (int*)(smem + SM_HB);
    int*   headS   = (int*)(smem + SM_HS);
    int*   headE   = (int*)(smem + SM_HE);
    float* cam  = smem + SM_CAM;
    float* in4  = smem + SM_IN4;
    int*   scal = (int*)(smem + SM_SCAL);   // [0]=nheads [1]=eqflag

    int blk = blockIdx.x;             // 176 = 2 batches * 88 columns
    int b = blk / FW, wi = blk % FW;
    int t = threadIdx.x;

    // stage precomputed tables (pure copies)
    for (int j = t; j < 3168; j += 1024)
        ((float4*)w2s)[j] = ((const float4*)g_w2f)[j];
    if (t < OUT2) c2s[t] = g_c2[t];
    if (t <= NR) radE[t] = g_radE[t];
    if (t >= 256 && t < 256 + NT + 1) angE[t - 256] = g_angE[t - 256];
    if (t < 9) cam[t] = rots[b*9 + t];
    if (t < 3) cam[9+t] = trans[b*3 + t];
    if (t == 0) {
        in4[0] = intr[b*9 + 0]; in4[1] = intr[b*9 + 4];
        in4[2] = intr[b*9 + 2]; in4[3] = intr[b*9 + 5];
        scal[0] = 0;
        scal[1] = (rots[b*9 + 1] == 0.f && rots[b*9 + 4] == 0.f) ? 1 : 0;
    }

    // load hidden for 32 rows of this column: hsh[row*HST + c]
    float* hsh = uni;
    if (t < 512) {
        int row = t >> 4, c4 = t & 15;
        ((float4*)&hsh[row*HST])[c4] = ((const float4*)&g_h[(b*PIX + row*FW + wi)*HID])[c4];
    }
    __syncthreads();

    // bins for row 0 (overlaps GEMM2 on MUFU/ALU pipes)
    if (t >= 512 && t < 512 + DEPTH)
        bins0[t - 512] = computeBin(wi, 0, t - 512, cam, in4, radE, angE);

    // GEMM2: 32 pixels x 198 outputs, f32x2; og 0..31, 7 accumulators
    int pix = t & 31, og = t >> 5;     // og warp-uniform -> broadcast weight LDS
    {
        u64 acc[7];
#pragma unroll
        for (int k = 0; k < 7; k++) acc[k] = 0;
        bool has7 = (og < 6);
#pragma unroll
        for (int c4 = 0; c4 < 16; c4++) {
            ulonglong2 h2 = *(const ulonglong2*)&hsh[pix*HST + c4*4];
#pragma unroll
            for (int k = 0; k < 6; k++) {
                ulonglong2 wv = *(const ulonglong2*)&w2s[(og + 32*k)*HID + c4*4];
                fma2(acc[k], wv.x, h2.x);
                fma2(acc[k], wv.y, h2.y);
            }
            if (has7) {
                ulonglong2 wv = *(const ulonglong2*)&w2s[(192 + og)*HID + c4*4];
                fma2(acc[6], wv.x, h2.x);
                fma2(acc[6], wv.y, h2.y);
            }
        }
#pragma unroll
        for (int k = 0; k < 6; k++) {
            int o = og + 32*k;
            float2 p = unpack2(acc[k]);
            int s = (o < DEPTH) ? o : o + 2;
            vsh[pix*VST + s] = p.x + p.y + c2s[o];
        }
        if (has7) {
            int o = 192 + og;
            float2 p = unpack2(acc[6]);
            vsh[pix*VST + o + 2] = p.x + p.y + c2s[o];
        }
    }
    __syncthreads();

    // softmax over depth: 32 warps, 1 pixel each
    int lane = t & 31, warp = t >> 5;
    {
        int p = warp;
        float a0 = vsh[p*VST + lane];
        float a1 = vsh[p*VST + lane + 32];
        float a2 = vsh[p*VST + lane + 64];
        float a3 = (lane + 96 < DEPTH) ? vsh[p*VST + lane + 96] : -INFINITY;
        float m = fmaxf(fmaxf(a0,a1), fmaxf(a2,a3));
#pragma unroll
        for (int s = 16; s; s >>= 1) m = fmaxf(m, __shfl_xor_sync(~0u, m, s));
        float e0 = __expf(a0 - m), e1 = __expf(a1 - m), e2 = __expf(a2 - m);
        float e3 = (lane + 96 < DEPTH) ? __expf(a3 - m) : 0.f;
        float sm = e0 + e1 + e2 + e3;
#pragma unroll
        for (int s = 16; s; s >>= 1) sm += __shfl_xor_sync(~0u, sm, s);
        float iv = 1.f / sm;
        vsh[p*VST + lane]      = e0*iv;
        vsh[p*VST + lane + 32] = e1*iv;
        vsh[p*VST + lane + 64] = e2*iv;
        if (lane + 96 < DEPTH) vsh[p*VST + lane + 96] = e3*iv;
    }
    __syncthreads();

    float* outb = out + b*C_OUT*NRT;

    if (scal[1]) {
        // run-compress row0 bins (row-independent)
        if (t < DEPTH) {
            int bn = bins0[t];
            if (bn >= 0 && (t == 0 || bins0[t-1] != bn)) {
                int k = t + 1;
                while (k < DEPTH && bins0[k] == bn) k++;
                int s = atomicAdd(&scal[0], 1);
                headBin[s] = bn; headS[s] = t; headE[s] = k;
            }
        }
        __syncthreads();
        int nh = scal[0];
        // per-head, per-row depth weight
        float* wsum = uni;   // hsh dead
        for (int i = t; i < nh*32; i += 1024) {
            int h = i >> 5, row = i & 31;
            float s = 0.f;
            for (int d = headS[h]; d < headE[h]; d++) s += vsh[row*VST + d];
            wsum[h*32 + row] = s;
        }
        __syncthreads();
        // aggregate 32 rows; 2 heads per thread; scalar REDs to final layout
        int npair = (nh + 1) >> 1;
        for (int i = t; i < npair*20; i += 1024) {
            int hp = i/20, q = i - hp*20;
            int h0 = hp*2, h1 = h0 + 1;
            bool two = (h1 < nh);
            float4 A = make_float4(0.f,0.f,0.f,0.f);
            float4 Bv = make_float4(0.f,0.f,0.f,0.f);
#pragma unroll 4
            for (int row = 0; row < 32; row++) {
                float4 f = *(const float4*)&vsh[row*VST + FOFF + q*4];
                float w0 = wsum[h0*32 + row];
                A.x += w0*f.x; A.y += w0*f.y; A.z += w0*f.z; A.w += w0*f.w;
                if (two) {
                    float w1 = wsum[h1*32 + row];
                    Bv.x += w1*f.x; Bv.y += w1*f.y; Bv.z += w1*f.z; Bv.w += w1*f.w;
                }
            }
            float* p0 = outb + (q*4)*NRT + headBin[h0];
            redadd(p0,          A.x);
            redadd(p0 +   NRT,  A.y);
            redadd(p0 + 2*NRT,  A.z);
            redadd(p0 + 3*NRT,  A.w);
            if (two) {
                float* p1 = outb + (q*4)*NRT + headBin[h1];
                redadd(p1,          Bv.x);
                redadd(p1 +   NRT,  Bv.y);
                redadd(p1 + 2*NRT,  Bv.z);
                redadd(p1 + 3*NRT,  Bv.w);
            }
        }
    } else {
        // generic fallback: per-row scatter
        for (int row = 0; row < 32; row++) {
            __syncthreads();
            if (t == 0) scal[0] = 0;
            __syncthreads();
            if (t < DEPTH) bins0[t] = computeBin(wi, row, t, cam, in4, radE, angE);
            __syncthreads();
            if (t < DEPTH) {
                int bn = bins0[t];
                if (bn >= 0 && (t == 0 || bins0[t-1] != bn)) {
                    int k = t + 1;
                    while (k < DEPTH && bins0[k] == bn) k++;
                    float s = 0.f;
                    for (int d = t; d < k; d++) s += vsh[row*VST + d];
                    int sN = atomicAdd(&scal[0], 1);
                    headBin[sN] = bn;
                    headS[sN] = __float_as_int(s);
                }
            }
            __syncthreads();
            int nh = scal[0];
            for (int i = t; i < nh*20; i += 1024) {
                int h = i/20, q = i - h*20;
                float w = __int_as_float(headS[h]);
                const float* f = &vsh[row*VST + FOFF + q*4];
                float* p0 = outb + (q*4)*NRT + headBin[h];
                redadd(p0,          w*f[0]);
                redadd(p0 +   NRT,  w*f[1]);
                redadd(p0 + 2*NRT,  w*f[2]);
                redadd(p0 + 3*NRT,  w*f[3]);
            }
        }
    }
}

// ---------------- launch ----------------
extern "C" void kernel_launch(void* const* d_in, const int* in_sizes, int n_in,
                              void* d_out, int out_size)
{
    const float* x     = (const float*)d_in[0];
    const float* rots  = (const float*)d_in[1];
    const float* trans = (const float*)d_in[2];
    const float* intr  = (const float*)d_in[3];
    const float* w1    = (const float*)d_in[4];
    const float* b1    = (const float*)d_in[5];
    const float* g1    = (const float*)d_in[6];
    const float* be1   = (const float*)d_in[7];
    const float* m1    = (const float*)d_in[8];
    const float* v1    = (const float*)d_in[9];
    const float* w2    = (const float*)d_in[10];
    const float* b2    = (const float*)d_in[11];
    const float* g2    = (const float*)d_in[12];
    const float* be2   = (const float*)d_in[13];
    const float* m2    = (const float*)d_in[14];
    const float* v2    = (const float*)d_in[15];
    float* out = (float*)d_out;

    static int configured = 0;
    if (!configured) {
        cudaFuncSetAttribute(k23_fused, cudaFuncAttributeMaxDynamicSharedMemorySize, K23_SMEM);
        configured = 1;
    }

    k1_gemm1<<<489, 256>>>(x, w1, b1, g1, be1, m1, v1,
                           w2, b2, g2, be2, m2, v2, out);
    k23_fused<<<176, 1024, K23_SMEM>>>(rots, trans, intr, out);
}

// round 16
// speedup vs baseline: 1.1981x; 1.0223x over previous
#include <cuda_runtime.h>
#include <math.h>

#define IH 256
#define IW 704
#define FH 32
#define FW 88
#define PIX (FH*FW)          // 2816
#define BATCH 2
#define C_IN 256
#define HID 64
#define DEPTH 118
#define C_OUT 80
#define OUT2 (DEPTH + C_OUT) // 198
#define NR 128
#define NT 256
#define NRT (NR*NT)          // 32768
#define PI_D 3.141592653589793
#define VST 204              // vsh row stride (feat at +120)
#define FOFF 120
#define HCST 132             // hsh2 per-c4 stride (conflict-free + 16B aligned)

typedef unsigned long long u64;

// ---------------- device scratch ----------------
__device__ float g_h[BATCH*PIX*HID];             // [b][pix][hid]
__device__ __align__(16) float g_w2f[OUT2*HID];  // BN-folded w2
__device__ float g_c2[OUT2];
__device__ float g_radE[NR+1];
__device__ float g_angE[NT+1];

// ---------------- f32x2 helpers ----------------
__device__ __forceinline__ void fma2(u64& d, u64 a, u64 b) {
    asm("fma.rn.f32x2 %0, %1, %2, %3;" : "=l"(d) : "l"(a), "l"(b), "l"(d));
}
__device__ __forceinline__ float2 unpack2(u64 v) {
    float2 r; asm("mov.b64 {%0,%1}, %2;" : "=f"(r.x), "=f"(r.y) : "l"(v)); return r;
}
__device__ __forceinline__ void redadd(float* p, float v) {
    asm volatile("red.global.add.f32 [%0], %1;" :: "l"(p), "f"(v) : "memory");
}

// ---------------- K1: GEMM1 + zero d_out + precompute tables / folded w2 (R6 version) ------
__global__ void __launch_bounds__(256) k1_gemm1(const float* __restrict__ x,
                                                const float* __restrict__ w1,
                                                const float* __restrict__ b1,
                                                const float* __restrict__ g1,
                                                const float* __restrict__ be1,
                                                const float* __restrict__ m1,
                                                const float* __restrict__ v1,
                                                const float* __restrict__ w2,
                                                const float* __restrict__ b2,
                                                const float* __restrict__ g2,
                                                const float* __restrict__ be2,
                                                const float* __restrict__ m2,
                                                const float* __restrict__ v2,
                                                float* __restrict__ outz)
{
    __shared__ float xs[64*16];      // [c][pix]
    __shared__ float ws[64*65];      // [c][o], stride 65

    int blk = blockIdx.x, t = threadIdx.x;

    if (blk >= 352) {
        if (blk < 480) {
            int base = (blk - 352) * 10240;
            float4 z = make_float4(0.f,0.f,0.f,0.f);
#pragma unroll 4
            for (int i = t; i < 10240; i += 256)
                ((float4*)outz)[base + i] = z;
        } else if (blk == 480) {
            if (t <= NR) {
                double tt = (double)t * (1.0/128.0);
                g_radE[t] = (float)(1.0 + pow(tt, 1.5) * 59.0);
            }
            for (int i = t; i <= NT; i += 256) {
                double a = (i == NT) ? (PI_D*0.5) : (-PI_D*0.5 + (double)i * (PI_D/256.0));
                g_angE[i] = (float)a;
            }
            if (t < OUT2) {
                float inv = g2[t] / sqrtf(v2[t] + 1e-5f);
                g_c2[t] = b2[t]*inv + be2[t] - m2[t]*inv;
            }
        } else {
            int base = (blk - 481) * 396;
            for (int j = base + t; j < base + 396; j += 256) {
                int o = j >> 4;
                float inv = g2[o] / sqrtf(v2[o] + 1e-5f);
                float4 w = ((const float4*)w2)[j];
                w.x *= inv; w.y *= inv; w.z *= inv; w.w *= inv;
                ((float4*)g_w2f)[j] = w;
            }
        }
        return;
    }

    int b = blk / 176;
    int pixbase = (blk % 176) * 16;
    int o  = t & 63;
    int pg = t >> 6;

    float4 acc = make_float4(0.f,0.f,0.f,0.f);

    for (int cc = 0; cc < 4; cc++) {
        __syncthreads();
        {
            int c = t >> 2, p4 = t & 3;
            ((float4*)xs)[t] = ((const float4*)(x + (b*C_IN + cc*64 + c)*PIX + pixbase))[p4];
        }
#pragma unroll
        for (int i = 0; i < 4; i++) {
            int j = t + i*256;
            int oo = j >> 4, k4 = j & 15;
            float4 w = *(const float4*)(w1 + oo*C_IN + cc*64 + k4*4);
            ws[(k4*4+0)*65 + oo] = w.x;
            ws[(k4*4+1)*65 + oo] = w.y;
            ws[(k4*4+2)*65 + oo] = w.z;
            ws[(k4*4+3)*65 + oo] = w.w;
        }
        __syncthreads();
#pragma unroll 8
        for (int cl = 0; cl < 64; cl++) {
            float w = ws[cl*65 + o];
            float4 xv = *(const float4*)&xs[cl*16 + pg*4];
            acc.x += w*xv.x; acc.y += w*xv.y; acc.z += w*xv.z; acc.w += w*xv.w;
        }
    }
    float inv  = g1[o] / sqrtf(v1[o] + 1e-5f);
    float bias = b1[o]*inv + be1[o] - m1[o]*inv;
    int pbase = b*PIX + pixbase + pg*4;
    g_h[(pbase+0)*HID + o] = fmaxf(acc.x*inv + bias, 0.f);
    g_h[(pbase+1)*HID + o] = fmaxf(acc.y*inv + bias, 0.f);
    g_h[(pbase+2)*HID + o] = fmaxf(acc.z*inv + bias, 0.f);
    g_h[(pbase+3)*HID + o] = fmaxf(acc.w*inv + bias, 0.f);
}

// ---------------- geometry helpers ----------------
__device__ __forceinline__ int upper_bound_sh(const float* a, int n, float v)
{
    int lo = 0, hi = n;
    while (lo < hi) {
        int m = (lo + hi) >> 1;
        if (a[m] <= v) lo = m + 1; else hi = m;
    }
    return lo;
}

__device__ __forceinline__ int computeBin(int wi, int row, int d,
                                          const float* cam, const float* in4,
                                          const float* radE, const float* angE)
{
    float u = (wi == FW-1) ? (float)(IW-1) : (float)((double)wi * ((double)(IW-1)/(FW-1)));
    float v = (row == FH-1) ? (float)(IH-1) : (float)((double)row * ((double)(IH-1)/(FH-1)));
    float dv = 1.0f + 0.5f * (float)d;
    float pcx = (u - in4[2]) * dv / in4[0];
    float pcy = (v - in4[3]) * dv / in4[1];
    float pcz = dv;
    float xl = cam[0]*pcx + cam[1]*pcy + cam[2]*pcz + cam[9];
    float yl = cam[3]*pcx + cam[4]*pcy + cam[5]*pcz + cam[10];
    float r  = sqrtf(xl*xl + yl*yl);
    float th = atan2f(yl, xl);
    int ri = upper_bound_sh(radE, NR+1, r)  - 1;
    int ti = upper_bound_sh(angE, NT+1, th) - 1;
    if (ri < 0 || ri >= NR || ti < 0 || ti >= NT) return -1;
    return ri*NT + ti;
}

// dynamic smem layout (floats)
#define SM_W2S   0                 // 12672
#define SM_C2S   12672             // 200
#define SM_VSH   12872             // 32*204 = 6528
#define SM_UNI   19400             // hsh2 16*132=2112 / wsum 118*32=3776
#define SM_RADE  23176             // 132
#define SM_ANGE  23308             // 260
#define SM_BINS  23568             // 120 (int)
#define SM_HB    23688             // 120
#define SM_HS    23808             // 120
#define SM_HE    23928             // 120
#define SM_CAM   24048             // 12
#define SM_IN4   24060             // 4
#define SM_SCAL  24064             // 4 ints
#define K23_FLOATS 24068
#define K23_SMEM (K23_FLOATS*4)

// ---------------- K23: GEMM2 + BN + softmax + lift + scatter; block = column, 1024 thr ------
__global__ void __launch_bounds__(1024, 1) k23_fused(const float* __restrict__ rots,
                                                     const float* __restrict__ trans,
                                                     const float* __restrict__ intr,
                                                     float* __restrict__ out)
{
    extern __shared__ float smem[];
    float* w2s  = smem + SM_W2S;
    float* c2s  = smem + SM_C2S;
    float* vsh  = smem + SM_VSH;
    float* uni  = smem + SM_UNI;
    float* radE = smem + SM_RADE;
    float* angE = smem + SM_ANGE;
    int*   bins0   = (int*)(smem + SM_BINS);
    int*   headBin = (int*)(smem + SM_HB);
    int*   headS   = (int*)(smem + SM_HS);
    int*   headE   = (int*)(smem + SM_HE);
    float* cam  = smem + SM_CAM;
    float* in4  = smem + SM_IN4;
    int*   scal = (int*)(smem + SM_SCAL);   // [0]=nheads [1]=eqflag

    int blk = blockIdx.x;             // 176 = 2 batches * 88 columns
    int b = blk / FW, wi = blk % FW;
    int t = threadIdx.x;

    // stage precomputed tables (pure copies)
    for (int j = t; j < 3168; j += 1024)
        ((float4*)w2s)[j] = ((const float4*)g_w2f)[j];
    if (t < OUT2) c2s[t] = g_c2[t];
    if (t <= NR) radE[t] = g_radE[t];
    if (t >= 256 && t < 256 + NT + 1) angE[t - 256] = g_angE[t - 256];
    if (t < 9) cam[t] = rots[b*9 + t];
    if (t < 3) cam[9+t] = trans[b*3 + t];
    if (t == 0) {
        in4[0] = intr[b*9 + 0]; in4[1] = intr[b*9 + 4];
        in4[2] = intr[b*9 + 2]; in4[3] = intr[b*9 + 5];
        scal[0] = 0;
        scal[1] = (rots[b*9 + 1] == 0.f && rots[b*9 + 4] == 0.f) ? 1 : 0;
    }

    // load hidden for 32 rows: hsh2[c4*HCST + pix*4 + j] (conflict-free GEMM reads)
    float* hsh2 = uni;
    if (t < 512) {
        int row = t >> 4, c4 = t & 15;
        float4 h = ((const float4*)&g_h[(b*PIX + row*FW + wi)*HID])[c4];
        *(float4*)&hsh2[c4*HCST + row*4] = h;
    }
    __syncthreads();

    // bins for row 0 (overlaps GEMM2 on MUFU/ALU pipes)
    if (t >= 512 && t < 512 + DEPTH)
        bins0[t - 512] = computeBin(wi, 0, t - 512, cam, in4, radE, angE);

    // GEMM2: 32 pixels x 198 outputs, f32x2; og 0..31, 7 accumulators
    int pix = t & 31, og = t >> 5;     // og warp-uniform -> broadcast weight LDS
    {
        u64 acc[7];
#pragma unroll
        for (int k = 0; k < 7; k++) acc[k] = 0;
        bool has7 = (og < 6);
#pragma unroll
        for (int c4 = 0; c4 < 16; c4++) {
            ulonglong2 h2 = *(const ulonglong2*)&hsh2[c4*HCST + pix*4];
#pragma unroll
            for (int k = 0; k < 6; k++) {
                ulonglong2 wv = *(const ulonglong2*)&w2s[(og + 32*k)*HID + c4*4];
                fma2(acc[k], wv.x, h2.x);
                fma2(acc[k], wv.y, h2.y);
            }
            if (has7) {
                ulonglong2 wv = *(const ulonglong2*)&w2s[(192 + og)*HID + c4*4];
                fma2(acc[6], wv.x, h2.x);
                fma2(acc[6], wv.y, h2.y);
            }
        }
#pragma unroll
        for (int k = 0; k < 6; k++) {
            int o = og + 32*k;
            float2 p = unpack2(acc[k]);
            int s = (o < DEPTH) ? o : o + 2;
            vsh[pix*VST + s] = p.x + p.y + c2s[o];
        }
        if (has7) {
            int o = 192 + og;
            float2 p = unpack2(acc[6]);
            vsh[pix*VST + o + 2] = p.x + p.y + c2s[o];
        }
    }
    __syncthreads();

    // softmax over depth: 32 warps, 1 pixel each
    int lane = t & 31, warp = t >> 5;
    {
        int p = warp;
        float a0 = vsh[p*VST + lane];
        float a1 = vsh[p*VST + lane + 32];
        float a2 = vsh[p*VST + lane + 64];
        float a3 = (lane + 96 < DEPTH) ? vsh[p*VST + lane + 96] : -INFINITY;
        float m = fmaxf(fmaxf(a0,a1), fmaxf(a2,a3));
#pragma unroll
        for (int s = 16; s; s >>= 1) m = fmaxf(m, __shfl_xor_sync(~0u, m, s));
        float e0 = __expf(a0 - m), e1 = __expf(a1 - m), e2 = __expf(a2 - m);
        float e3 = (lane + 96 < DEPTH) ? __expf(a3 - m) : 0.f;
        float sm = e0 + e1 + e2 + e3;
#pragma unroll
        for (int s = 16; s; s >>= 1) sm += __shfl_xor_sync(~0u, sm, s);
        float iv = 1.f / sm;
        vsh[p*VST + lane]      = e0*iv;
        vsh[p*VST + lane + 32] = e1*iv;
        vsh[p*VST + lane + 64] = e2*iv;
        if (lane + 96 < DEPTH) vsh[p*VST + lane + 96] = e3*iv;
    }
    __syncthreads();

    float* outb = out + b*C_OUT*NRT;

    if (scal[1]) {
        // run-compress row0 bins (row-independent)
        if (t < DEPTH) {
            int bn = bins0[t];
            if (bn >= 0 && (t == 0 || bins0[t-1] != bn)) {
                int k = t + 1;
                while (k < DEPTH && bins0[k] == bn) k++;
                int s = atomicAdd(&scal[0], 1);
                headBin[s] = bn; headS[s] = t; headE[s] = k;
            }
        }
        __syncthreads();
        int nh = scal[0];
        // per-head, per-row depth weight
        float* wsum = uni;   // hsh2 dead
        for (int i = t; i < nh*32; i += 1024) {
            int h = i >> 5, row = i & 31;
            float s = 0.f;
            for (int d = headS[h]; d < headE[h]; d++) s += vsh[row*VST + d];
            wsum[h*32 + row] = s;
        }
        __syncthreads();
        // aggregate 32 rows; 2 heads per thread; scalar REDs to final layout
        int npair = (nh + 1) >> 1;
        for (int i = t; i < npair*20; i += 1024) {
            int hp = i/20, q = i - hp*20;
            int h0 = hp*2, h1 = h0 + 1;
            bool two = (h1 < nh);
            float4 A = make_float4(0.f,0.f,0.f,0.f);
            float4 Bv = make_float4(0.f,0.f,0.f,0.f);
#pragma unroll 4
            for (int row = 0; row < 32; row++) {
                float4 f = *(const float4*)&vsh[row*VST + FOFF + q*4];
                float w0 = wsum[h0*32 + row];
                A.x += w0*f.x; A.y += w0*f.y; A.z += w0*f.z; A.w += w0*f.w;
                if (two) {
                    float w1 = wsum[h1*32 + row];
                    Bv.x += w1*f.x; Bv.y += w1*f.y; Bv.z += w1*f.z; Bv.w += w1*f.w;
                }
            }
            float* p0 = outb + (q*4)*NRT + headBin[h0];
            redadd(p0,          A.x);
            redadd(p0 +   NRT,  A.y);
            redadd(p0 + 2*NRT,  A.z);
            redadd(p0 + 3*NRT,  A.w);
            if (two) {
                float* p1 = outb + (q*4)*NRT + headBin[h1];
                redadd(p1,          Bv.x);
                redadd(p1 +   NRT,  Bv.y);
                redadd(p1 + 2*NRT,  Bv.z);
                redadd(p1 + 3*NRT,  Bv.w);
            }
        }
    } else {
        // generic fallback: per-row scatter
        for (int row = 0; row < 32; row++) {
            __syncthreads();
            if (t == 0) scal[0] = 0;
            __syncthreads();
            if (t < DEPTH) bins0[t] = computeBin(wi, row, t, cam, in4, radE, angE);
            __syncthreads();
            if (t < DEPTH) {
                int bn = bins0[t];
                if (bn >= 0 && (t == 0 || bins0[t-1] != bn)) {
                    int k = t + 1;
                    while (k < DEPTH && bins0[k] == bn) k++;
                    float s = 0.f;
                    for (int d = t; d < k; d++) s += vsh[row*VST + d];
                    int sN = atomicAdd(&scal[0], 1);
                    headBin[sN] = bn;
                    headS[sN] = __float_as_int(s);
                }
            }
            __syncthreads();
            int nh = scal[0];
            for (int i = t; i < nh*20; i += 1024) {
                int h = i/20, q = i - h*20;
                float w = __int_as_float(headS[h]);
                const float* f = &vsh[row*VST + FOFF + q*4];
                float* p0 = outb + (q*4)*NRT + headBin[h];
                redadd(p0,          w*f[0]);
                redadd(p0 +   NRT,  w*f[1]);
                redadd(p0 + 2*NRT,  w*f[2]);
                redadd(p0 + 3*NRT,  w*f[3]);
            }
        }
    }
}

// ---------------- launch ----------------
extern "C" void kernel_launch(void* const* d_in, const int* in_sizes, int n_in,
                              void* d_out, int out_size)
{
    const float* x     = (const float*)d_in[0];
    const float* rots  = (const float*)d_in[1];
    const float* trans = (const float*)d_in[2];
    const float* intr  = (const float*)d_in[3];
    const float* w1    = (const float*)d_in[4];
    const float* b1    = (const float*)d_in[5];
    const float* g1    = (const float*)d_in[6];
    const float* be1   = (const float*)d_in[7];
    const float* m1    = (const float*)d_in[8];
    const float* v1    = (const float*)d_in[9];
    const float* w2    = (const float*)d_in[10];
    const float* b2    = (const float*)d_in[11];
    const float* g2    = (const float*)d_in[12];
    const float* be2   = (const float*)d_in[13];
    const float* m2    = (const float*)d_in[14];
    const float* v2    = (const float*)d_in[15];
    float* out = (float*)d_out;

    static int configured = 0;
    if (!configured) {
        cudaFuncSetAttribute(k23_fused, cudaFuncAttributeMaxDynamicSharedMemorySize, K23_SMEM);
        configured = 1;
    }

    k1_gemm1<<<489, 256>>>(x, w1, b1, g1, be1, m1, v1,
                           w2, b2, g2, be2, m2, v2, out);
    k23_fused<<<176, 1024, K23_SMEM>>>(rots, trans, intr, out);
}